// round 3
// baseline (speedup 1.0000x reference)
#include <cuda_runtime.h>
#include <math.h>

#define NQ   10
#define DIM  1024
#define NP   64
#define DF   10
#define NL   5
#define NBLK 64
#define NT   512

#define TWOPI   6.2831853071795864769f
#define INV2PI  0.15915494309189533577f

// Scratch (no allocations allowed)
__device__ float2   g_states[NP * DIM];   // psi(x_p), 512 KB
__device__ float    g_K[NP * NP];
__device__ unsigned g_bar1 = 0, g_bar2 = 0;

// Software grid barrier: valid because grid (64) < #SMs (148) -> single wave,
// all blocks co-resident. Counters are reset by block 0 at the end of every
// launch, so graph replays see a clean state.
__device__ __forceinline__ void grid_arrive_wait(unsigned* ctr, bool wait)
{
    __syncthreads();
    if (threadIdx.x == 0) {
        __threadfence();
        atomicAdd(ctr, 1u);
        if (wait) {
            while (*(volatile unsigned*)ctr < NBLK) { }
            __threadfence();
        }
    }
    __syncthreads();
}

// ------------------------------------------------------------------------
// One fused kernel: phase 1 simulate psi(x_p) (one block per point),
// grid barrier, phase 2 gram tile per block, grid barrier, phase 3
// finalize on block 0 (deterministic double reduction).
//
// Sim amplitude mapping: idx = (r<<9) | t, r in [0,2) = qubit 9 (register),
// t bits 0-4 = lane (qubits 0-4, shfl), t bits 5-8 = warp (qubits 5-8,
// one combined 16-way shared exchange per gate pass).
// H normalization (2^-5 per layer, exact) folded into the layer-invariant
// rz diagonal factors, precomputed once.
// ------------------------------------------------------------------------
__global__ __launch_bounds__(NT) void fused_kernel(
    const float* __restrict__ data,     // (NP, DF)
    const float* __restrict__ labels,   // (NP,)
    const float* __restrict__ params,   // (NL, 2, NQ)
    float* __restrict__ out)
{
    __shared__ __align__(16) float pool[8192];            // 32 KB, multi-use
    __shared__ float xs[16];                              // xs[q] = x[9-q]
    __shared__ float ryc[NL][NQ], rys[NL][NQ], phi[NL][NQ];

    const int p    = blockIdx.x;
    const int t    = threadIdx.x;
    const int lane = t & 31;
    const int w    = t >> 5;                  // 16 warps
    const int b5 = w & 1, b6 = (w >> 1) & 1, b7 = (w >> 2) & 1, b8 = (w >> 3) & 1;

    if (t < NQ) xs[t] = data[p * DF + (NQ - 1 - t)];
    if (t >= 32 && t < 32 + NL * NQ) {
        int u = t - 32, l = u / NQ, m = u % NQ;
        float s, c;
        sincosf(0.5f * params[l * 2 * NQ + m], &s, &c);
        ryc[l][m] = c;  rys[l][m] = s;
        phi[l][m] = params[l * 2 * NQ + NQ + m];
    }
    __syncthreads();

    // ---------------- phase 1: simulation ----------------
    float re[2], im[2];
    re[0] = (t == 0) ? 1.f : 0.f;  re[1] = 0.f;
    im[0] = 0.f;                   im[1] = 0.f;

    // rz diagonal factors (layer-invariant), scaled by 2^-5
    float rzc[2], rzs[2];
    {
        float base = 0.f;
        #pragma unroll
        for (int q = 0; q < NQ; ++q) base -= 0.5f * xs[q];
        #pragma unroll
        for (int q = 0; q < 9; ++q) if ((t >> q) & 1) base += xs[q];
        #pragma unroll
        for (int r = 0; r < 2; ++r) {
            float ang = base + (r ? xs[9] : 0.f);
            ang = fmaf(-TWOPI, rintf(ang * INV2PI), ang);
            float s, c;
            __sincosf(ang, &s, &c);
            rzc[r] = c * 0.03125f;
            rzs[r] = s * 0.03125f;
        }
    }

    // H exchange signs (layer-invariant): parity of AND(my warp bits, partner bits)
    float hsgn[16];
    #pragma unroll
    for (int pw = 0; pw < 16; ++pw) {
        int par = (b5 & (pw & 1)) ^ (b6 & ((pw >> 1) & 1)) ^
                  (b7 & ((pw >> 2) & 1)) ^ (b8 & ((pw >> 3) & 1));
        hsgn[pw] = par ? -1.f : 1.f;
    }

    float* sb0 = pool;            // 512*5 = 2560 floats
    float* sb1 = pool + 2560;
    const float b8f = (float)((t >> 8) & 1);
    const float bt0 = (t & 1) ? 0.5f : -0.5f;

    #pragma unroll 1
    for (int l = 0; l < NL; ++l) {
        // ---- H on qubits 0-4 (shfl butterflies, unnormalized) ----
        #pragma unroll
        for (int q = 0; q < 5; ++q) {
            float sgn = ((lane >> q) & 1) ? -1.f : 1.f;
            #pragma unroll
            for (int r = 0; r < 2; ++r) {
                float o = __shfl_xor_sync(0xffffffffu, re[r], 1 << q);
                re[r] = fmaf(sgn, re[r], o);
                o = __shfl_xor_sync(0xffffffffu, im[r], 1 << q);
                im[r] = fmaf(sgn, im[r], o);
            }
        }
        // ---- H on qubit 9 (in-register) ----
        {
            float a = re[0], b = re[1];
            re[0] = a + b;  re[1] = a - b;
            a = im[0];  b = im[1];
            im[0] = a + b;  im[1] = a - b;
        }
        // ---- H on qubits 5-8: combined 16-way cross-warp exchange ----
        {
            float* my = sb0 + t * 5;
            my[0] = re[0]; my[1] = re[1]; my[2] = im[0]; my[3] = im[1];
            __syncthreads();
            float r0 = 0.f, r1 = 0.f, i0 = 0.f, i1 = 0.f;
            #pragma unroll
            for (int pw = 0; pw < 16; ++pw) {
                const float* pr = sb0 + (lane + (pw << 5)) * 5;
                r0 = fmaf(hsgn[pw], pr[0], r0);
                r1 = fmaf(hsgn[pw], pr[1], r1);
                i0 = fmaf(hsgn[pw], pr[2], i0);
                i1 = fmaf(hsgn[pw], pr[3], i1);
            }
            re[0] = r0; re[1] = r1; im[0] = i0; im[1] = i1;
        }
        // ---- rz diagonal (precomputed, includes 2^-5) ----
        #pragma unroll
        for (int r = 0; r < 2; ++r) {
            float nr = re[r] * rzc[r] - im[r] * rzs[r];
            im[r]    = re[r] * rzs[r] + im[r] * rzc[r];
            re[r]    = nr;
        }
        // ---- RY on qubits 0-4 (shfl) ----
        #pragma unroll
        for (int q = 0; q < 5; ++q) {
            float c  = ryc[l][q];
            float ss = ((lane >> q) & 1) ? rys[l][q] : -rys[l][q];
            #pragma unroll
            for (int r = 0; r < 2; ++r) {
                float o = __shfl_xor_sync(0xffffffffu, re[r], 1 << q);
                re[r] = fmaf(c, re[r], ss * o);
                o = __shfl_xor_sync(0xffffffffu, im[r], 1 << q);
                im[r] = fmaf(c, im[r], ss * o);
            }
        }
        // ---- RY on qubit 9 (in-register) ----
        {
            float c = ryc[l][9], s = rys[l][9];
            float a0 = re[0], a1 = re[1];
            re[0] = c * a0 - s * a1;  re[1] = s * a0 + c * a1;
            a0 = im[0];  a1 = im[1];
            im[0] = c * a0 - s * a1;  im[1] = s * a0 + c * a1;
        }
        // ---- RY on qubits 5-8: combined 16-way exchange ----
        {
            float m5[2], m6[2], m7[2], m8[2];
            m5[b5] = ryc[l][5];  m5[b5 ^ 1] = b5 ? rys[l][5] : -rys[l][5];
            m6[b6] = ryc[l][6];  m6[b6 ^ 1] = b6 ? rys[l][6] : -rys[l][6];
            m7[b7] = ryc[l][7];  m7[b7 ^ 1] = b7 ? rys[l][7] : -rys[l][7];
            m8[b8] = ryc[l][8];  m8[b8 ^ 1] = b8 ? rys[l][8] : -rys[l][8];
            float coef[16];
            #pragma unroll
            for (int pw = 0; pw < 16; ++pw)
                coef[pw] = m5[pw & 1] * m6[(pw >> 1) & 1] *
                           m7[(pw >> 2) & 1] * m8[(pw >> 3) & 1];
            float* my = sb1 + t * 5;
            my[0] = re[0]; my[1] = re[1]; my[2] = im[0]; my[3] = im[1];
            __syncthreads();
            float r0 = 0.f, r1 = 0.f, i0 = 0.f, i1 = 0.f;
            #pragma unroll
            for (int pw = 0; pw < 16; ++pw) {
                const float* pr = sb1 + (lane + (pw << 5)) * 5;
                r0 = fmaf(coef[pw], pr[0], r0);
                r1 = fmaf(coef[pw], pr[1], r1);
                i0 = fmaf(coef[pw], pr[2], i0);
                i1 = fmaf(coef[pw], pr[3], i1);
            }
            re[0] = r0; re[1] = r1; im[0] = i0; im[1] = i1;
        }
        // ---- crz ring diagonal ----
        {
            float angT = 0.f;
            #pragma unroll
            for (int m = 0; m < 8; ++m)
                if ((t >> m) & 1)
                    angT += (((t >> (m + 1)) & 1) ? 0.5f : -0.5f) * phi[l][m];
            #pragma unroll
            for (int r = 0; r < 2; ++r) {
                float b9 = (float)r;
                float ang = angT
                          + b8f * (b9 - 0.5f) * phi[l][8]
                          + b9 * bt0 * phi[l][9];
                ang = fmaf(-TWOPI, rintf(ang * INV2PI), ang);
                float s, c;
                __sincosf(ang, &s, &c);
                float nr = re[r] * c - im[r] * s;
                im[r]    = re[r] * s + im[r] * c;
                re[r]    = nr;
            }
        }
    }

    #pragma unroll
    for (int r = 0; r < 2; ++r)
        g_states[p * DIM + (r << 9) + t] = make_float2(re[r], im[r]);

    // ---------------- grid barrier 1 (all wait) ----------------
    grid_arrive_wait(&g_bar1, true);

    // ---------------- phase 2: gram tile (8x8 pairs per block) ----------------
    {
        float2* As = (float2*)pool;        // 8 x 256 float2 = 16 KB
        float2* Bs = As + 2048;            // 16 KB
        const int i0 = (blockIdx.x >> 3) * 8;
        const int j0 = (blockIdx.x & 7) * 8;
        const int g  = t >> 5;             // 16 groups -> 4x4 grid of 2x2 tiles
        const int ks = lane;
        const int py = (g >> 2) * 2;
        const int px = (g & 3) * 2;

        float aR[2][2] = {{0.f,0.f},{0.f,0.f}};
        float aI[2][2] = {{0.f,0.f},{0.f,0.f}};

        for (int kc = 0; kc < 4; ++kc) {
            const int kb = kc * 256;
            #pragma unroll
            for (int idx = 0; idx < 2048; idx += NT) {
                int e = idx + t;
                int row = e >> 8, col = e & 255;
                As[row * 256 + col] = g_states[(i0 + row) * DIM + kb + col];
                Bs[row * 256 + col] = g_states[(j0 + row) * DIM + kb + col];
            }
            __syncthreads();
            #pragma unroll 4
            for (int k = ks; k < 256; k += 32) {
                float2 a0 = As[py * 256 + k],       a1 = As[(py + 1) * 256 + k];
                float2 b0 = Bs[px * 256 + k],       b1 = Bs[(px + 1) * 256 + k];
                aR[0][0] += b0.x*a0.x + b0.y*a0.y;  aI[0][0] += b0.x*a0.y - b0.y*a0.x;
                aR[0][1] += b1.x*a0.x + b1.y*a0.y;  aI[0][1] += b1.x*a0.y - b1.y*a0.x;
                aR[1][0] += b0.x*a1.x + b0.y*a1.y;  aI[1][0] += b0.x*a1.y - b0.y*a1.x;
                aR[1][1] += b1.x*a1.x + b1.y*a1.y;  aI[1][1] += b1.x*a1.y - b1.y*a1.x;
            }
            __syncthreads();
        }

        #pragma unroll
        for (int off = 16; off; off >>= 1) {
            #pragma unroll
            for (int di = 0; di < 2; ++di)
                #pragma unroll
                for (int dj = 0; dj < 2; ++dj) {
                    aR[di][dj] += __shfl_down_sync(0xffffffffu, aR[di][dj], off);
                    aI[di][dj] += __shfl_down_sync(0xffffffffu, aI[di][dj], off);
                }
        }
        if (ks == 0) {
            #pragma unroll
            for (int di = 0; di < 2; ++di)
                #pragma unroll
                for (int dj = 0; dj < 2; ++dj) {
                    float R = aR[di][dj], I = aI[di][dj];
                    g_K[(i0 + py + di) * NP + (j0 + px + dj)] = R * R + I * I;
                }
        }
    }

    // ---------------- grid barrier 2 (only block 0 waits) ----------------
    grid_arrive_wait(&g_bar2, blockIdx.x == 0);

    // ---------------- phase 3: finalize (block 0) ----------------
    if (blockIdx.x == 0) {
        double* skp = (double*)pool;       // 512 doubles
        double* skk = skp + NT;            // 512 doubles (8 KB total, fits)
        double kp = 0.0, kk = 0.0;
        for (int pidx = t; pidx < NP * NP; pidx += NT) {
            int i = pidx >> 6, j = pidx & 63;
            double k  = (double)g_K[pidx];
            double lm = (double)labels[i] * (double)labels[j];
            kp += lm * k;
            kk += k * k;
        }
        skp[t] = kp;  skk[t] = kk;
        __syncthreads();
        for (int s = NT / 2; s; s >>= 1) {
            if (t < s) { skp[t] += skp[t + s]; skk[t] += skk[t + s]; }
            __syncthreads();
        }
        if (t == 0) {
            double sl2 = 0.0;
            for (int i = 0; i < NP; ++i) {
                double l = (double)labels[i];
                sl2 += l * l;
            }
            out[0] = (float)(skp[0] / sqrt(skk[0] * sl2 * sl2));
            g_bar1 = 0;         // reset for next graph replay
            g_bar2 = 0;
            __threadfence();
        }
    }
}

// ------------------------------------------------------------------------
extern "C" void kernel_launch(void* const* d_in, const int* in_sizes, int n_in,
                              void* d_out, int out_size)
{
    const float* data   = (const float*)d_in[0];   // (64, 10)
    const float* labels = (const float*)d_in[1];   // (64,)
    const float* params = (const float*)d_in[2];   // (5, 2, 10)
    float* out = (float*)d_out;

    fused_kernel<<<NBLK, NT>>>(data, labels, params, out);
}

// round 5
// speedup vs baseline: 1.2375x; 1.2375x over previous
#include <cuda_runtime.h>
#include <math.h>

#define NQ   10
#define DIM  1024
#define NP   64
#define DF   10
#define NL   5
#define NBLK 136          // = 16*17/2 triangle tiles; > 64 sim blocks; < 148 SMs (single wave)
#define NT   256

#define TWOPI   6.2831853071795864769f
#define INV2PI  0.15915494309189533577f
#define EXS     12        // exchange buffer stride in floats (48B: float4-friendly, conflict-light)

// Scratch (no device allocations allowed)
__device__ __align__(16) float2 g_states[NP * DIM];   // psi(x_p), 512 KB
__device__ float    g_K[NP * NP];
__device__ unsigned g_bar1 = 0, g_bar2 = 0;

__device__ __forceinline__ void grid_arrive_wait(unsigned* ctr, bool wait)
{
    __syncthreads();
    if (threadIdx.x == 0) {
        __threadfence();
        atomicAdd(ctr, 1u);
        if (wait) {
            while (*(volatile unsigned*)ctr < NBLK) { __nanosleep(64); }
            __threadfence();
        }
    }
    __syncthreads();
}

__device__ __forceinline__ void cmul(float ar, float ai, float br, float bi,
                                     float& cr, float& ci)
{
    cr = ar * br - ai * bi;
    ci = ar * bi + ai * br;
}

// ============================================================================
// Fused: phase1 sim (blocks 0-63) | grid bar | phase2 gram (136 triangle
// tiles, one per block) | grid bar | phase3 finalize (block 0).
//
// Sim amp index = (r<<8)|t : r bit0 = qubit 8, r bit1 = qubit 9 (registers);
// t bits 0-4 = lane (qubits 0-4, shfl); t bits 5-7 = warp (qubits 5-7, one
// flat 8-way shared exchange per layer, double buffered -> 1 barrier/layer).
// Composed gate U_q = RY(theta)*RZ(alpha)*H (incl. 1/sqrt2) per (layer,qubit)
// precomputed in shared. Layer 0 on |0> built directly from column 0 of U.
// ============================================================================
__global__ __launch_bounds__(NT) void fused_kernel(
    const float* __restrict__ data,     // (NP, DF)
    const float* __restrict__ labels,   // (NP,)
    const float* __restrict__ params,   // (NL, 2, NQ)
    float* __restrict__ out)
{
    __shared__ float Ug[NL][NQ][8];     // [u00r,u00i,u01r,u01i,u10r,u10i,u11r,u11i]
    __shared__ float phis[NL][NQ];
    __shared__ __align__(16) float ebuf[2][NT * EXS]; // 24 KB exchange buffers
    __shared__ double fin[2 * NT];      // finalize reduction

    const int p    = blockIdx.x;
    const int t    = threadIdx.x;
    const int lane = t & 31;
    const int w    = t >> 5;            // 8 warps

    // ---------------- phase 1: simulation (blocks 0-63) ----------------
    if (p < NP) {
        // build composed gates + ring params
        if (t < NL * NQ) {
            const int l = t / NQ, q = t % NQ;
            const float alpha = data[p * DF + (NQ - 1 - q)];   // xs[q] = x[9-q]
            const float theta = params[l * 2 * NQ + q];
            float s, c, sa, ca;
            sincosf(0.5f * theta, &s, &c);
            sincosf(0.5f * alpha, &sa, &ca);
            const float INV_S2 = 0.70710678118654752440f;
            float* U = &Ug[l][q][0];
            U[0] = (c - s) * ca * INV_S2;   U[1] = -(c + s) * sa * INV_S2;  // u00
            U[2] = (c + s) * ca * INV_S2;   U[3] =  (s - c) * sa * INV_S2;  // u01
            U[4] = (s + c) * ca * INV_S2;   U[5] =  (c - s) * sa * INV_S2;  // u10
            U[6] = (s - c) * ca * INV_S2;   U[7] = -(s + c) * sa * INV_S2;  // u11
            phis[l][q] = params[l * 2 * NQ + NQ + q];
        }
        __syncthreads();

        // ring-coefficient precompute (layer-invariant, from t bits 0-7)
        float cring[7];
        #pragma unroll
        for (int m = 0; m < 7; ++m) {
            float bm  = (float)((t >> m) & 1);
            float bm1 = (float)((t >> (m + 1)) & 1);
            cring[m] = bm * (bm1 - 0.5f);
        }
        const float c7  = (float)((t >> 7) & 1);
        const float c9a = (float)(t & 1) - 0.5f;

        float re[4], im[4];

        // ---- layer 0 from |0>: amp = prod_q U_q[b_q][0], then ring ----
        {
            float cr = 1.f, ci = 0.f;
            #pragma unroll
            for (int q = 0; q < 8; ++q) {
                int b = (t >> q) & 1;
                const float* Uq = &Ug[0][q][0];
                float nr, ni;
                cmul(cr, ci, Uq[b * 4], Uq[b * 4 + 1], nr, ni);
                cr = nr;  ci = ni;
            }
            float c8r[2], c8i[2];
            #pragma unroll
            for (int j = 0; j < 2; ++j)
                cmul(cr, ci, Ug[0][8][j * 4], Ug[0][8][j * 4 + 1], c8r[j], c8i[j]);
            #pragma unroll
            for (int r = 0; r < 4; ++r)
                cmul(c8r[r & 1], c8i[r & 1],
                     Ug[0][9][(r >> 1) * 4], Ug[0][9][(r >> 1) * 4 + 1],
                     re[r], im[r]);
        }
        // per-layer: ring diag then (next layer's) composed gates
        #pragma unroll 1
        for (int l = 0; ; ) {
            {
                float angT = 0.f;
                #pragma unroll
                for (int m = 0; m < 7; ++m) angT = fmaf(cring[m], phis[l][m], angT);
                const float p7 = phis[l][7], p8 = phis[l][8], p9 = phis[l][9];
                #pragma unroll
                for (int r = 0; r < 4; ++r) {
                    float f8 = (float)(r & 1), f9 = (float)(r >> 1);
                    float ang = angT;
                    ang = fmaf(c7 * (f8 - 0.5f), p7, ang);
                    ang = fmaf(f8 * (f9 - 0.5f), p8, ang);
                    ang = fmaf(f9 * c9a,         p9, ang);
                    ang = fmaf(-TWOPI, rintf(ang * INV2PI), ang);
                    float s, c;
                    __sincosf(ang, &s, &c);
                    float nr = re[r] * c - im[r] * s;
                    im[r]    = re[r] * s + im[r] * c;
                    re[r]    = nr;
                }
            }
            if (++l >= NL) break;

            // ---- composed gates, layer l ----
            // lane qubits 0-4 (shfl butterflies)
            #pragma unroll
            for (int q = 0; q < 5; ++q) {
                const int b = (lane >> q) & 1;
                const float* Uq = &Ug[l][q][0];
                const float ur = Uq[b * 6],     ui = Uq[b * 6 + 1];
                const float vr = Uq[2 + b * 2], vi = Uq[3 + b * 2];
                #pragma unroll
                for (int r = 0; r < 4; ++r) {
                    float pre = __shfl_xor_sync(0xffffffffu, re[r], 1 << q);
                    float pim = __shfl_xor_sync(0xffffffffu, im[r], 1 << q);
                    float nr = ur * re[r] - ui * im[r] + vr * pre - vi * pim;
                    float ni = ur * im[r] + ui * re[r] + vr * pim + vi * pre;
                    re[r] = nr;  im[r] = ni;
                }
            }
            // reg qubit 8: pairs (0,1),(2,3); reg qubit 9: pairs (0,2),(1,3)
            {
                const float* U8 = &Ug[l][8][0];
                #pragma unroll
                for (int j = 0; j < 4; j += 2) {
                    float a0r = re[j], a0i = im[j], a1r = re[j+1], a1i = im[j+1];
                    re[j]   = U8[0]*a0r - U8[1]*a0i + U8[2]*a1r - U8[3]*a1i;
                    im[j]   = U8[0]*a0i + U8[1]*a0r + U8[2]*a1i + U8[3]*a1r;
                    re[j+1] = U8[4]*a0r - U8[5]*a0i + U8[6]*a1r - U8[7]*a1i;
                    im[j+1] = U8[4]*a0i + U8[5]*a0r + U8[6]*a1i + U8[7]*a1r;
                }
                const float* U9 = &Ug[l][9][0];
                #pragma unroll
                for (int j = 0; j < 2; ++j) {
                    float a0r = re[j], a0i = im[j], a1r = re[j+2], a1i = im[j+2];
                    re[j]   = U9[0]*a0r - U9[1]*a0i + U9[2]*a1r - U9[3]*a1i;
                    im[j]   = U9[0]*a0i + U9[1]*a0r + U9[2]*a1i + U9[3]*a1r;
                    re[j+2] = U9[4]*a0r - U9[5]*a0i + U9[6]*a1r - U9[7]*a1i;
                    im[j+2] = U9[4]*a0i + U9[5]*a0r + U9[6]*a1i + U9[7]*a1r;
                }
            }
            // warp qubits 5-7: flat 8-way exchange with complex tensor coefs
            {
                const int b5 = w & 1, b6 = (w >> 1) & 1, b7 = (w >> 2) & 1;
                float a5r[2], a5i[2], a6r[2], a6i[2], a7r[2], a7i[2];
                #pragma unroll
                for (int pp = 0; pp < 2; ++pp) {
                    a5r[pp] = Ug[l][5][(b5*2+pp)*2];  a5i[pp] = Ug[l][5][(b5*2+pp)*2+1];
                    a6r[pp] = Ug[l][6][(b6*2+pp)*2];  a6i[pp] = Ug[l][6][(b6*2+pp)*2+1];
                    a7r[pp] = Ug[l][7][(b7*2+pp)*2];  a7i[pp] = Ug[l][7][(b7*2+pp)*2+1];
                }
                float Cr[8], Ci[8];
                #pragma unroll
                for (int pw = 0; pw < 8; ++pw) {
                    float t1r, t1i;
                    cmul(a5r[pw & 1], a5i[pw & 1],
                         a6r[(pw >> 1) & 1], a6i[(pw >> 1) & 1], t1r, t1i);
                    cmul(t1r, t1i, a7r[pw >> 2], a7i[pw >> 2], Cr[pw], Ci[pw]);
                }
                float* my = &ebuf[l & 1][t * EXS];
                *(float4*)(my)     = make_float4(re[0], re[1], re[2], re[3]);
                *(float4*)(my + 4) = make_float4(im[0], im[1], im[2], im[3]);
                __syncthreads();
                float nr[4] = {0.f,0.f,0.f,0.f}, ni[4] = {0.f,0.f,0.f,0.f};
                #pragma unroll
                for (int pw = 0; pw < 8; ++pw) {
                    const float* pr = &ebuf[l & 1][((pw << 5) | lane) * EXS];
                    float4 vre = *(const float4*)(pr);
                    float4 vim = *(const float4*)(pr + 4);
                    const float cr = Cr[pw], cc = Ci[pw];
                    nr[0] += cr*vre.x - cc*vim.x;  ni[0] += cr*vim.x + cc*vre.x;
                    nr[1] += cr*vre.y - cc*vim.y;  ni[1] += cr*vim.y + cc*vre.y;
                    nr[2] += cr*vre.z - cc*vim.z;  ni[2] += cr*vim.z + cc*vre.z;
                    nr[3] += cr*vre.w - cc*vim.w;  ni[3] += cr*vim.w + cc*vre.w;
                }
                #pragma unroll
                for (int r = 0; r < 4; ++r) { re[r] = nr[r]; im[r] = ni[r]; }
            }
        }

        #pragma unroll
        for (int r = 0; r < 4; ++r)
            g_states[p * DIM + (r << 8) + t] = make_float2(re[r], im[r]);
    }

    // ---------------- grid barrier 1 ----------------
    grid_arrive_wait(&g_bar1, true);

    // ---------------- phase 2: gram, 136 upper-triangle 4x4 tiles ----------------
    {
        int rem = blockIdx.x, gi = 0;
        while (rem >= 16 - gi) { rem -= 16 - gi; ++gi; }
        const int gj = gi + rem;
        const int i  = gi * 4 + (w >> 1);
        const int j0 = gj * 4 + 2 * (w & 1);

        const float2* __restrict__ A  = g_states + i * DIM;
        const float2* __restrict__ B0 = g_states + j0 * DIM;
        const float2* __restrict__ B1 = g_states + (j0 + 1) * DIM;

        float r0 = 0.f, i0a = 0.f, r1 = 0.f, i1a = 0.f;
        #pragma unroll 4
        for (int kk = 0; kk < 16; ++kk) {
            const int k = kk * 64 + lane * 2;
            float4 a  = *(const float4*)&A[k];     // (re0,im0,re1,im1)
            float4 b0 = *(const float4*)&B0[k];
            float4 b1 = *(const float4*)&B1[k];
            // conj(b) * a, two k's
            r0  += b0.x*a.x + b0.y*a.y + b0.z*a.z + b0.w*a.w;
            i0a += b0.x*a.y - b0.y*a.x + b0.z*a.w - b0.w*a.z;
            r1  += b1.x*a.x + b1.y*a.y + b1.z*a.z + b1.w*a.w;
            i1a += b1.x*a.y - b1.y*a.x + b1.z*a.w - b1.w*a.z;
        }
        #pragma unroll
        for (int off = 16; off; off >>= 1) {
            r0  += __shfl_down_sync(0xffffffffu, r0,  off);
            i0a += __shfl_down_sync(0xffffffffu, i0a, off);
            r1  += __shfl_down_sync(0xffffffffu, r1,  off);
            i1a += __shfl_down_sync(0xffffffffu, i1a, off);
        }
        if (lane == 0) {
            float k0 = r0 * r0 + i0a * i0a;
            float k1 = r1 * r1 + i1a * i1a;
            g_K[i * NP + j0]       = k0;
            g_K[i * NP + j0 + 1]   = k1;
            g_K[j0 * NP + i]       = k0;   // |conj| symmetric
            g_K[(j0 + 1) * NP + i] = k1;
        }
    }

    // ---------------- grid barrier 2 (only block 0 waits) ----------------
    grid_arrive_wait(&g_bar2, blockIdx.x == 0);

    // ---------------- phase 3: finalize (block 0) ----------------
    if (blockIdx.x == 0) {
        double* skp = fin;
        double* skk = fin + NT;
        double kp = 0.0, kk = 0.0;
        for (int pidx = t; pidx < NP * NP; pidx += NT) {
            int i = pidx >> 6, j = pidx & 63;
            double k  = (double)g_K[pidx];
            double lm = (double)labels[i] * (double)labels[j];
            kp += lm * k;
            kk += k * k;
        }
        skp[t] = kp;  skk[t] = kk;
        __syncthreads();
        for (int s = NT / 2; s; s >>= 1) {
            if (t < s) { skp[t] += skp[t + s]; skk[t] += skk[t + s]; }
            __syncthreads();
        }
        if (t == 0) {
            double sl2 = 0.0;
            for (int i = 0; i < NP; ++i) {
                double l = (double)labels[i];
                sl2 += l * l;
            }
            out[0] = (float)(skp[0] / sqrt(skk[0] * sl2 * sl2));
            g_bar1 = 0;        // reset for next graph replay
            g_bar2 = 0;
            __threadfence();
        }
    }
}

// ----------------------------------------------------------------------------
extern "C" void kernel_launch(void* const* d_in, const int* in_sizes, int n_in,
                              void* d_out, int out_size)
{
    const float* data   = (const float*)d_in[0];   // (64, 10)
    const float* labels = (const float*)d_in[1];   // (64,)
    const float* params = (const float*)d_in[2];   // (5, 2, 10)
    float* out = (float*)d_out;

    fused_kernel<<<NBLK, NT>>>(data, labels, params, out);
}

// round 6
// speedup vs baseline: 1.5153x; 1.2245x over previous
#include <cuda_runtime.h>
#include <math.h>

#define NQ   10
#define DIM  1024
#define NP   64
#define DF   10
#define NL   5
#define NBLK 136          // 16*17/2 triangle tiles; single wave (<148 SMs)
#define NT   256

#define TWOPI   6.2831853071795864769f
#define INV2PI  0.15915494309189533577f
#define EXS     12        // exchange stride in floats (48B, float4-aligned per thread)

// Scratch (no device allocations allowed)
__device__ __align__(16) float2 g_states[NP * DIM];   // psi(x_p), 512 KB
__device__ double   g_part[NBLK][2];                  // per-block (kp, kk)
__device__ unsigned g_ready = 0;                      // sim-done counter (target 64)
__device__ unsigned g_done  = 0;                      // gram-done ticket (target NBLK)

__device__ __forceinline__ void cmul(float ar, float ai, float br, float bi,
                                     float& cr, float& ci)
{
    cr = ar * br - ai * bi;
    ci = ar * bi + ai * br;
}

// ============================================================================
// Fused single kernel:
//  phase 1: blocks 0-63 simulate psi(x_p); signal g_ready.
//  wait:    all blocks wait g_ready == 64.
//  phase 2: each of 136 blocks computes one upper-triangle 4x4 gram tile and
//           accumulates its kp/kk contribution (deterministic in-block tree),
//           writes g_part[blockIdx].
//  tail:    last block (atomicInc ticket) reduces 136 partials in a fixed
//           tree and writes out; resets counters for graph replay.
//
// Sim amp index = (r<<8)|t : r bits = qubits 8,9 (registers); t bits 0-4 =
// lane (qubits 0-4, shfl); t bits 5-7 = warp (qubits 5-7, one flat 8-way
// shared exchange per layer). Composed gate U = RY*RZ*H (incl 1/sqrt2).
// ============================================================================
__global__ __launch_bounds__(NT) void fused_kernel(
    const float* __restrict__ data,     // (NP, DF)
    const float* __restrict__ labels,   // (NP,)
    const float* __restrict__ params,   // (NL, 2, NQ)
    float* __restrict__ out)
{
    __shared__ float Ug[NL][NQ][8];     // composed gates
    __shared__ float phis[NL][NQ];
    __shared__ float2 Cx[NL * 64];      // exchange coefs [l][w][pw]
    __shared__ __align__(16) float ebuf[2][NT * EXS];   // 24 KB
    __shared__ double wacc[8][2];       // per-warp gram partials
    __shared__ double red[NT][2];       // last-block reduction

    const int p    = blockIdx.x;
    const int t    = threadIdx.x;
    const int lane = t & 31;
    const int w    = t >> 5;            // 8 warps

    // ---------------- phase 1: simulation (blocks 0-63) ----------------
    if (p < NP) {
        if (t < NL * NQ) {
            const int l = t / NQ, q = t % NQ;
            const float alpha = data[p * DF + (NQ - 1 - q)];
            const float theta = params[l * 2 * NQ + q];
            float s, c, sa, ca;
            sincosf(0.5f * theta, &s, &c);
            sincosf(0.5f * alpha, &sa, &ca);
            const float INV_S2 = 0.70710678118654752440f;
            float* U = &Ug[l][q][0];
            U[0] = (c - s) * ca * INV_S2;   U[1] = -(c + s) * sa * INV_S2;  // u00
            U[2] = (c + s) * ca * INV_S2;   U[3] =  (s - c) * sa * INV_S2;  // u01
            U[4] = (s + c) * ca * INV_S2;   U[5] =  (c - s) * sa * INV_S2;  // u10
            U[6] = (s - c) * ca * INV_S2;   U[7] = -(s + c) * sa * INV_S2;  // u11
            phis[l][q] = params[l * 2 * NQ + NQ + q];
        }
        __syncthreads();

        // exchange coefficients: Cx[l][w][pw] = U5[b5][pw0]*U6[b6][pw1]*U7[b7][pw2]
        for (int e = t; e < NL * 64; e += NT) {
            const int l  = e >> 6;
            const int ww = (e >> 3) & 7;
            const int pw = e & 7;
            const int b5 = ww & 1, b6 = (ww >> 1) & 1, b7 = (ww >> 2) & 1;
            const float* U5 = &Ug[l][5][(2 * b5 + (pw & 1)) * 2];
            const float* U6 = &Ug[l][6][(2 * b6 + ((pw >> 1) & 1)) * 2];
            const float* U7 = &Ug[l][7][(2 * b7 + (pw >> 2)) * 2];
            float t1r, t1i, cr, ci;
            cmul(U5[0], U5[1], U6[0], U6[1], t1r, t1i);
            cmul(t1r, t1i, U7[0], U7[1], cr, ci);
            Cx[e] = make_float2(cr, ci);
        }

        // ring-coefficient precompute (layer-invariant)
        float cring[7];
        #pragma unroll
        for (int m = 0; m < 7; ++m) {
            float bm  = (float)((t >> m) & 1);
            float bm1 = (float)((t >> (m + 1)) & 1);
            cring[m] = bm * (bm1 - 0.5f);
        }
        const float c7  = (float)((t >> 7) & 1);
        const float c9a = (float)(t & 1) - 0.5f;
        __syncthreads();

        float re[4], im[4];

        // ---- layer 0 from |0>: amp = prod_q U_q[b_q][0] ----
        {
            float cr = 1.f, ci = 0.f;
            #pragma unroll
            for (int q = 0; q < 8; ++q) {
                int b = (t >> q) & 1;
                const float* Uq = &Ug[0][q][0];
                float nr, ni;
                cmul(cr, ci, Uq[b * 4], Uq[b * 4 + 1], nr, ni);
                cr = nr;  ci = ni;
            }
            float c8r[2], c8i[2];
            #pragma unroll
            for (int j = 0; j < 2; ++j)
                cmul(cr, ci, Ug[0][8][j * 4], Ug[0][8][j * 4 + 1], c8r[j], c8i[j]);
            #pragma unroll
            for (int r = 0; r < 4; ++r)
                cmul(c8r[r & 1], c8i[r & 1],
                     Ug[0][9][(r >> 1) * 4], Ug[0][9][(r >> 1) * 4 + 1],
                     re[r], im[r]);
        }

        #pragma unroll 1
        for (int l = 0; ; ) {
            // ---- crz ring diagonal, layer l ----
            {
                float angT = 0.f;
                #pragma unroll
                for (int m = 0; m < 7; ++m) angT = fmaf(cring[m], phis[l][m], angT);
                const float p7 = phis[l][7], p8 = phis[l][8], p9 = phis[l][9];
                #pragma unroll
                for (int r = 0; r < 4; ++r) {
                    float f8 = (float)(r & 1), f9 = (float)(r >> 1);
                    float ang = angT;
                    ang = fmaf(c7 * (f8 - 0.5f), p7, ang);
                    ang = fmaf(f8 * (f9 - 0.5f), p8, ang);
                    ang = fmaf(f9 * c9a,         p9, ang);
                    ang = fmaf(-TWOPI, rintf(ang * INV2PI), ang);
                    float s, c;
                    __sincosf(ang, &s, &c);
                    float nr = re[r] * c - im[r] * s;
                    im[r]    = re[r] * s + im[r] * c;
                    re[r]    = nr;
                }
            }
            if (++l >= NL) break;

            // ---- lane qubits 0-4 (shfl butterflies) ----
            #pragma unroll
            for (int q = 0; q < 5; ++q) {
                const int b = (lane >> q) & 1;
                const float* Uq = &Ug[l][q][0];
                const float ur = Uq[b * 6],     ui = Uq[b * 6 + 1];
                const float vr = Uq[2 + b * 2], vi = Uq[3 + b * 2];
                #pragma unroll
                for (int r = 0; r < 4; ++r) {
                    float pre = __shfl_xor_sync(0xffffffffu, re[r], 1 << q);
                    float pim = __shfl_xor_sync(0xffffffffu, im[r], 1 << q);
                    float nr = ur * re[r] - ui * im[r] + vr * pre - vi * pim;
                    float ni = ur * im[r] + ui * re[r] + vr * pim + vi * pre;
                    re[r] = nr;  im[r] = ni;
                }
            }
            // ---- reg qubits 8, 9 ----
            {
                const float* U8 = &Ug[l][8][0];
                #pragma unroll
                for (int j = 0; j < 4; j += 2) {
                    float a0r = re[j], a0i = im[j], a1r = re[j+1], a1i = im[j+1];
                    re[j]   = U8[0]*a0r - U8[1]*a0i + U8[2]*a1r - U8[3]*a1i;
                    im[j]   = U8[0]*a0i + U8[1]*a0r + U8[2]*a1i + U8[3]*a1r;
                    re[j+1] = U8[4]*a0r - U8[5]*a0i + U8[6]*a1r - U8[7]*a1i;
                    im[j+1] = U8[4]*a0i + U8[5]*a0r + U8[6]*a1i + U8[7]*a1r;
                }
                const float* U9 = &Ug[l][9][0];
                #pragma unroll
                for (int j = 0; j < 2; ++j) {
                    float a0r = re[j], a0i = im[j], a1r = re[j+2], a1i = im[j+2];
                    re[j]   = U9[0]*a0r - U9[1]*a0i + U9[2]*a1r - U9[3]*a1i;
                    im[j]   = U9[0]*a0i + U9[1]*a0r + U9[2]*a1i + U9[3]*a1r;
                    re[j+2] = U9[4]*a0r - U9[5]*a0i + U9[6]*a1r - U9[7]*a1i;
                    im[j+2] = U9[4]*a0i + U9[5]*a0r + U9[6]*a1i + U9[7]*a1r;
                }
            }
            // ---- warp qubits 5-7: flat 8-way exchange (precomputed coefs) ----
            {
                float* my = &ebuf[l & 1][t * EXS];
                *(float4*)(my)     = make_float4(re[0], re[1], re[2], re[3]);
                *(float4*)(my + 4) = make_float4(im[0], im[1], im[2], im[3]);
                __syncthreads();
                float nr[4] = {0.f,0.f,0.f,0.f}, ni[4] = {0.f,0.f,0.f,0.f};
                const float2* cw = &Cx[(l << 6) | (w << 3)];
                #pragma unroll
                for (int pw = 0; pw < 8; ++pw) {
                    const float* pr = &ebuf[l & 1][((pw << 5) | lane) * EXS];
                    float4 vre = *(const float4*)(pr);
                    float4 vim = *(const float4*)(pr + 4);
                    const float cr = cw[pw].x, cc = cw[pw].y;
                    nr[0] += cr*vre.x - cc*vim.x;  ni[0] += cr*vim.x + cc*vre.x;
                    nr[1] += cr*vre.y - cc*vim.y;  ni[1] += cr*vim.y + cc*vre.y;
                    nr[2] += cr*vre.z - cc*vim.z;  ni[2] += cr*vim.z + cc*vre.z;
                    nr[3] += cr*vre.w - cc*vim.w;  ni[3] += cr*vim.w + cc*vre.w;
                }
                #pragma unroll
                for (int r = 0; r < 4; ++r) { re[r] = nr[r]; im[r] = ni[r]; }
            }
        }

        #pragma unroll
        for (int r = 0; r < 4; ++r)
            g_states[p * DIM + (r << 8) + t] = make_float2(re[r], im[r]);

        // signal this state is visible
        __syncthreads();
        if (t == 0) {
            __threadfence();
            atomicAdd(&g_ready, 1u);
        }
    }

    // ---------------- wait for all 64 states ----------------
    if (t == 0) {
        while (*(volatile unsigned*)&g_ready < NP) { __nanosleep(64); }
        __threadfence();
    }
    __syncthreads();

    // ---------------- phase 2: gram tile + local KTA contribution ----------------
    {
        int rem = blockIdx.x, gi = 0;
        while (rem >= 16 - gi) { rem -= 16 - gi; ++gi; }
        const int gj = gi + rem;
        const int i  = gi * 4 + (w >> 1);
        const int j0 = gj * 4 + 2 * (w & 1);
        const double f = (gi == gj) ? 1.0 : 2.0;   // triangle symmetry factor

        const float2* __restrict__ A  = g_states + i * DIM;
        const float2* __restrict__ B0 = g_states + j0 * DIM;
        const float2* __restrict__ B1 = g_states + (j0 + 1) * DIM;

        float r0 = 0.f, i0a = 0.f, r1 = 0.f, i1a = 0.f;
        #pragma unroll 4
        for (int kk = 0; kk < 16; ++kk) {
            const int k = kk * 64 + lane * 2;
            float4 a  = *(const float4*)&A[k];
            float4 b0 = *(const float4*)&B0[k];
            float4 b1 = *(const float4*)&B1[k];
            r0  += b0.x*a.x + b0.y*a.y + b0.z*a.z + b0.w*a.w;
            i0a += b0.x*a.y - b0.y*a.x + b0.z*a.w - b0.w*a.z;
            r1  += b1.x*a.x + b1.y*a.y + b1.z*a.z + b1.w*a.w;
            i1a += b1.x*a.y - b1.y*a.x + b1.z*a.w - b1.w*a.z;
        }
        #pragma unroll
        for (int off = 16; off; off >>= 1) {
            r0  += __shfl_down_sync(0xffffffffu, r0,  off);
            i0a += __shfl_down_sync(0xffffffffu, i0a, off);
            r1  += __shfl_down_sync(0xffffffffu, r1,  off);
            i1a += __shfl_down_sync(0xffffffffu, i1a, off);
        }
        if (lane == 0) {
            double k0 = (double)r0 * r0 + (double)i0a * i0a;
            double k1 = (double)r1 * r1 + (double)i1a * i1a;
            double li  = (double)labels[i];
            double lj0 = (double)labels[j0];
            double lj1 = (double)labels[j0 + 1];
            wacc[w][0] = f * (li * lj0 * k0 + li * lj1 * k1);
            wacc[w][1] = f * (k0 * k0 + k1 * k1);
        }
        __syncthreads();
        if (t == 0) {
            double kp = 0.0, kk = 0.0;
            #pragma unroll
            for (int ww = 0; ww < 8; ++ww) { kp += wacc[ww][0]; kk += wacc[ww][1]; }
            g_part[blockIdx.x][0] = kp;
            g_part[blockIdx.x][1] = kk;
        }
    }

    // ---------------- tail: last block reduces 136 partials ----------------
    __shared__ unsigned s_last;
    if (t == 0) {
        __threadfence();
        s_last = (atomicInc(&g_done, NBLK - 1) == NBLK - 1) ? 1u : 0u;
    }
    __syncthreads();

    if (s_last) {
        if (t < NBLK) {
            red[t][0] = g_part[t][0];
            red[t][1] = g_part[t][1];
        } else {
            red[t][0] = 0.0;
            red[t][1] = 0.0;
        }
        __syncthreads();
        for (int s = NT / 2; s; s >>= 1) {
            if (t < s) { red[t][0] += red[t + s][0]; red[t][1] += red[t + s][1]; }
            __syncthreads();
        }
        if (t == 0) {
            double sl2 = 0.0;
            for (int i = 0; i < NP; ++i) {
                double l = (double)labels[i];
                sl2 += l * l;
            }
            out[0] = (float)(red[0][0] / sqrt(red[0][1] * sl2 * sl2));
            g_ready = 0;          // reset for next graph replay
            g_done  = 0;
            __threadfence();
        }
    }
}

// ----------------------------------------------------------------------------
extern "C" void kernel_launch(void* const* d_in, const int* in_sizes, int n_in,
                              void* d_out, int out_size)
{
    const float* data   = (const float*)d_in[0];   // (64, 10)
    const float* labels = (const float*)d_in[1];   // (64,)
    const float* params = (const float*)d_in[2];   // (5, 2, 10)
    float* out = (float*)d_out;

    fused_kernel<<<NBLK, NT>>>(data, labels, params, out);
}